// round 5
// baseline (speedup 1.0000x reference)
#include <cuda_runtime.h>
#include <cuda_bf16.h>

#define NN 50000
#define EE 800000
#define DD 128

// ---------------- scratch (device globals: no allocation allowed) ----------
__device__ float g_bufA[(size_t)NN * DD];   // GEMM output g (per layer)
__device__ float g_bufB[(size_t)NN * DD];   // aggregated h (layer 1)
__device__ int   g_cnt[NN];                 // per-dst edge count (excl self-loop)
__device__ int   g_rowstart[NN];
__device__ int   g_fill[NN];
__device__ int2  g_edge[EE];                // decoded (src, dst)
__device__ int   g_csr[EE];                 // src indices grouped by dst
__device__ int   g_is64;

// ---------------- f32x2 helpers (sm_103a packed fp32) ----------------------
__device__ __forceinline__ unsigned long long pack2(float lo, float hi) {
    unsigned long long r;
    asm("mov.b64 %0, {%1, %2};" : "=l"(r) : "f"(lo), "f"(hi));
    return r;
}
__device__ __forceinline__ void unpack2(unsigned long long v, float& lo, float& hi) {
    asm("mov.b64 {%0, %1}, %2;" : "=f"(lo), "=f"(hi) : "l"(v));
}
__device__ __forceinline__ void fma2(unsigned long long& acc,
                                     unsigned long long a, unsigned long long b) {
    asm("fma.rn.f32x2 %0, %1, %2, %3;" : "=l"(acc) : "l"(a), "l"(b), "l"(acc));
}

// ---------------- (1) dtype detect + cnt init -------------------------------
// edge_index declared int64, but JAX w/o x64 silently emits int32. For int64
// LE values < 50000, every odd 32-bit word is 0.
__global__ void detect_init_kernel(const int* __restrict__ ei32, int n) {
    int i = blockIdx.x * blockDim.x + threadIdx.x;
    if (i < n) g_cnt[i] = 0;
    if (i == 0) {
        int is64 = 1;
        for (int k = 0; k < 64; k++)
            if (ei32[2 * k + 1] != 0) { is64 = 0; break; }
        g_is64 = is64;
    }
}

// ---------------- (2) decode edges + dst histogram ---------------------------
__global__ void prep_edges_kernel(const void* __restrict__ ei_raw, int E, int n) {
    int e = blockIdx.x * blockDim.x + threadIdx.x;
    if (e >= E) return;
    int s, d;
    if (g_is64) {
        const long long* ei = (const long long*)ei_raw;
        s = (int)ei[e];
        d = (int)ei[(size_t)E + e];
    } else {
        const int* ei = (const int*)ei_raw;
        s = ei[e];
        d = ei[(size_t)E + e];
    }
    if (s < 0) s = 0; if (s >= n) s = n - 1;
    if (d < 0) d = 0; if (d >= n) d = n - 1;
    g_edge[e] = make_int2(s, d);
    atomicAdd(&g_cnt[d], 1);
}

// ---------------- (3) single-block scan: rowstart / fill ---------------------
__global__ void __launch_bounds__(1024) scan_kernel(int n) {
    __shared__ int sums[1024];
    const int T = 1024;
    int tid = threadIdx.x;
    int per = (n + T - 1) / T;
    int start = tid * per;
    int end = start + per; if (end > n) end = n;

    int s = 0;
    for (int i = start; i < end; i++) s += g_cnt[i];
    sums[tid] = s;
    __syncthreads();
    for (int off = 1; off < T; off <<= 1) {
        int v = 0;
        if (tid >= off) v = sums[tid - off];
        __syncthreads();
        if (tid >= off) sums[tid] += v;
        __syncthreads();
    }
    int run = (tid == 0) ? 0 : sums[tid - 1];
    for (int i = start; i < end; i++) {
        g_rowstart[i] = run;
        g_fill[i]     = run;
        run += g_cnt[i];
    }
}

// ---------------- (4) reorder into CSR (grouped by dst) ----------------------
__global__ void reorder_kernel(int E) {
    int e = blockIdx.x * blockDim.x + threadIdx.x;
    if (e >= E) return;
    int2 ed = g_edge[e];
    int idx = atomicAdd(&g_fill[ed.y], 1);
    g_csr[idx] = ed.x;
}

// ---------------- fused GEMM -------------------------------------------------
// g[r][c] = dis[r] * sum_k pre(X[r][k]) * W[k][c],  dis[r] = rsqrt(cnt[r]+1)
// pre(x)  = PRE ? relu(dis[r]*x + preb[k]) : x
template <bool PRE>
__global__ void __launch_bounds__(256) gemm_kernel(
    const float* __restrict__ X, const float* __restrict__ W,
    const float* __restrict__ preb, float* __restrict__ gout, int n)
{
    __shared__ float Xs[64 * DD];

    const int tid  = threadIdx.x;
    const int row0 = blockIdx.x * 64;

    const float4* X4  = (const float4*)X;
    float4*       Xs4 = (float4*)Xs;
    #pragma unroll
    for (int i = tid; i < 64 * 32; i += 256) {
        int r  = i >> 5;
        int c4 = i & 31;
        int gr = row0 + r;
        float4 v = make_float4(0.f, 0.f, 0.f, 0.f);
        if (gr < n) {
            v = X4[(size_t)gr * 32 + c4];
            if (PRE) {
                float dr = rsqrtf((float)(__ldg(&g_cnt[gr]) + 1));
                float4 bb = ((const float4*)preb)[c4];
                v.x = fmaxf(fmaf(dr, v.x, bb.x), 0.f);
                v.y = fmaxf(fmaf(dr, v.y, bb.y), 0.f);
                v.z = fmaxf(fmaf(dr, v.z, bb.z), 0.f);
                v.w = fmaxf(fmaf(dr, v.w, bb.w), 0.f);
            }
        }
        Xs4[i] = v;
    }
    __syncthreads();

    const int tx = tid & 31;
    const int ty = tid >> 5;

    unsigned long long accr[8][2];
    #pragma unroll
    for (int r = 0; r < 8; r++) { accr[r][0] = 0ull; accr[r][1] = 0ull; }

    const float4* W4 = (const float4*)W;
    #pragma unroll 8
    for (int k = 0; k < DD; k++) {
        float4 w = __ldg(&W4[k * 32 + tx]);
        unsigned long long w0 = pack2(w.x, w.y);
        unsigned long long w1 = pack2(w.z, w.w);
        #pragma unroll
        for (int r = 0; r < 8; r++) {
            float xv = Xs[(ty * 8 + r) * DD + k];
            unsigned long long xp = pack2(xv, xv);
            fma2(accr[r][0], xp, w0);
            fma2(accr[r][1], xp, w1);
        }
    }

    #pragma unroll
    for (int r = 0; r < 8; r++) {
        int gr = row0 + ty * 8 + r;
        if (gr < n) {
            float ds = rsqrtf((float)(__ldg(&g_cnt[gr]) + 1));
            float a0, a1, a2, a3;
            unpack2(accr[r][0], a0, a1);
            unpack2(accr[r][1], a2, a3);
            ((float4*)gout)[(size_t)gr * 32 + tx] =
                make_float4(a0 * ds, a1 * ds, a2 * ds, a3 * ds);
        }
    }
}

// ---------------- gather v2: warp per dst, 8-deep load batches ---------------
// out[d] = self + sum_{s in N(d)} g[s]                 (FIN=false)
// out[d] = relu(dis[d]*(self+sum) + bias)              (FIN=true)
template <bool FIN>
__global__ void __launch_bounds__(256) gather_kernel(
    const float* __restrict__ g, float* __restrict__ out,
    const float* __restrict__ bias, int n)
{
    int warp = (blockIdx.x * blockDim.x + threadIdx.x) >> 5;
    int lane = threadIdx.x & 31;
    if (warp >= n) return;
    const int d = warp;

    const float4* __restrict__ g4 = (const float4*)g;

    float4 acc = g4[(size_t)d * 32 + lane];   // self-loop message

    const int cnt = g_cnt[d];
    const int* __restrict__ lst = g_csr + g_rowstart[d];

    int j = 0;
    // 8-deep batches: 8 independent LDG.128 in flight before any accumulate
    for (; j + 8 <= cnt; j += 8) {
        int i0 = lst[j+0], i1 = lst[j+1], i2 = lst[j+2], i3 = lst[j+3];
        int i4 = lst[j+4], i5 = lst[j+5], i6 = lst[j+6], i7 = lst[j+7];
        float4 t0 = g4[(size_t)i0 * 32 + lane];
        float4 t1 = g4[(size_t)i1 * 32 + lane];
        float4 t2 = g4[(size_t)i2 * 32 + lane];
        float4 t3 = g4[(size_t)i3 * 32 + lane];
        float4 t4 = g4[(size_t)i4 * 32 + lane];
        float4 t5 = g4[(size_t)i5 * 32 + lane];
        float4 t6 = g4[(size_t)i6 * 32 + lane];
        float4 t7 = g4[(size_t)i7 * 32 + lane];
        // pairwise tree to shorten dependency chains
        float4 s01, s23, s45, s67, sA, sB;
        s01.x = t0.x + t1.x; s01.y = t0.y + t1.y; s01.z = t0.z + t1.z; s01.w = t0.w + t1.w;
        s23.x = t2.x + t3.x; s23.y = t2.y + t3.y; s23.z = t2.z + t3.z; s23.w = t2.w + t3.w;
        s45.x = t4.x + t5.x; s45.y = t4.y + t5.y; s45.z = t4.z + t5.z; s45.w = t4.w + t5.w;
        s67.x = t6.x + t7.x; s67.y = t6.y + t7.y; s67.z = t6.z + t7.z; s67.w = t6.w + t7.w;
        sA.x = s01.x + s23.x; sA.y = s01.y + s23.y; sA.z = s01.z + s23.z; sA.w = s01.w + s23.w;
        sB.x = s45.x + s67.x; sB.y = s45.y + s67.y; sB.z = s45.z + s67.z; sB.w = s45.w + s67.w;
        acc.x += sA.x + sB.x; acc.y += sA.y + sB.y;
        acc.z += sA.z + sB.z; acc.w += sA.w + sB.w;
    }
    if (j + 4 <= cnt) {
        int i0 = lst[j+0], i1 = lst[j+1], i2 = lst[j+2], i3 = lst[j+3];
        float4 t0 = g4[(size_t)i0 * 32 + lane];
        float4 t1 = g4[(size_t)i1 * 32 + lane];
        float4 t2 = g4[(size_t)i2 * 32 + lane];
        float4 t3 = g4[(size_t)i3 * 32 + lane];
        acc.x += (t0.x + t1.x) + (t2.x + t3.x);
        acc.y += (t0.y + t1.y) + (t2.y + t3.y);
        acc.z += (t0.z + t1.z) + (t2.z + t3.z);
        acc.w += (t0.w + t1.w) + (t2.w + t3.w);
        j += 4;
    }
    for (; j < cnt; j++) {
        float4 t = g4[(size_t)lst[j] * 32 + lane];
        acc.x += t.x; acc.y += t.y; acc.z += t.z; acc.w += t.w;
    }

    if (FIN) {
        float ds = rsqrtf((float)(cnt + 1));
        float4 bb = ((const float4*)bias)[lane];
        acc.x = fmaxf(fmaf(ds, acc.x, bb.x), 0.f);
        acc.y = fmaxf(fmaf(ds, acc.y, bb.y), 0.f);
        acc.z = fmaxf(fmaf(ds, acc.z, bb.z), 0.f);
        acc.w = fmaxf(fmaf(ds, acc.w, bb.w), 0.f);
    }
    ((float4*)out)[(size_t)d * 32 + lane] = acc;
}

// ---------------- launch -----------------------------------------------------
extern "C" void kernel_launch(void* const* d_in, const int* in_sizes, int n_in,
                              void* d_out, int out_size)
{
    const float* x   = (const float*)d_in[0];
    const void*  ei  = d_in[1];
    const float* W1  = (const float*)d_in[2];
    const float* b1  = (const float*)d_in[3];
    const float* W2  = (const float*)d_in[4];
    const float* b2  = (const float*)d_in[5];
    float*       out = (float*)d_out;

    const int n = in_sizes[0] / DD;   // 50000
    const int E = in_sizes[1] / 2;    // 800000

    void *pA = nullptr, *pB = nullptr;
    cudaGetSymbolAddress(&pA, g_bufA);
    cudaGetSymbolAddress(&pB, g_bufB);
    float* bufA = (float*)pA;
    float* bufB = (float*)pB;

    const int T = 256;
    const int gemm_grid   = (n + 63) / 64;
    const int gather_grid = (n * 32 + T - 1) / T;

    // CSR build
    detect_init_kernel<<<(n + T - 1) / T, T>>>((const int*)ei, n);   // (1)
    prep_edges_kernel<<<(E + T - 1) / T, T>>>(ei, E, n);             // (2)
    scan_kernel<<<1, 1024>>>(n);                                     // (3)
    reorder_kernel<<<(E + T - 1) / T, T>>>(E);                       // (4)

    // layer 1
    gemm_kernel<false><<<gemm_grid, T>>>(x, W1, nullptr, bufA, n);   // (5)
    gather_kernel<false><<<gather_grid, T>>>(bufA, bufB, nullptr, n);// (6) <- profiled

    // layer 2 (relu(dis*h+b1) fused into tile load; finalize fused into gather)
    gemm_kernel<true><<<gemm_grid, T>>>(bufB, W2, b1, bufA, n);      // (7)
    gather_kernel<true><<<gather_grid, T>>>(bufA, out, b2, n);       // (8)
}

// round 6
// speedup vs baseline: 1.3012x; 1.3012x over previous
#include <cuda_runtime.h>
#include <cuda_bf16.h>

#define NN 50000
#define EE 800000
#define DD 128

// ---------------- scratch (device globals: no allocation allowed) ----------
__device__ float g_bufA[(size_t)NN * DD];   // GEMM output g (per layer)
__device__ float g_bufB[(size_t)NN * DD];   // layer-1 accumulator
__device__ int   g_deg[NN];
__device__ int2  g_edge[EE];                // (src, dst)
__device__ int   g_is64;

// ---------------- f32x2 helpers (sm_103a packed fp32) ----------------------
__device__ __forceinline__ unsigned long long pack2(float lo, float hi) {
    unsigned long long r;
    asm("mov.b64 %0, {%1, %2};" : "=l"(r) : "f"(lo), "f"(hi));
    return r;
}
__device__ __forceinline__ void unpack2(unsigned long long v, float& lo, float& hi) {
    asm("mov.b64 {%0, %1}, %2;" : "=f"(lo), "=f"(hi) : "l"(v));
}
__device__ __forceinline__ void fma2(unsigned long long& acc,
                                     unsigned long long a, unsigned long long b) {
    asm("fma.rn.f32x2 %0, %1, %2, %3;" : "=l"(acc) : "l"(a), "l"(b), "l"(acc));
}

// ---------------- kernel 1: dtype detect + deg init -------------------------
// edge_index declared int64, but JAX w/o x64 silently emits int32. For int64
// LE values < 50000, every odd 32-bit word is 0.
__global__ void detect_init_kernel(const int* __restrict__ ei32, int n) {
    int i = blockIdx.x * blockDim.x + threadIdx.x;
    if (i < n) g_deg[i] = 1;  // self-loop
    if (i == 0) {
        int is64 = 1;
        for (int k = 0; k < 64; k++)
            if (ei32[2 * k + 1] != 0) { is64 = 0; break; }
        g_is64 = is64;
    }
}

// ---------------- kernel 2: decode edges + dst degree ------------------------
__global__ void prep_edges_kernel(const void* __restrict__ ei_raw, int E, int n) {
    int e = blockIdx.x * blockDim.x + threadIdx.x;
    if (e >= E) return;
    int s, d;
    if (g_is64) {
        const long long* ei = (const long long*)ei_raw;
        s = (int)ei[e];
        d = (int)ei[(size_t)E + e];
    } else {
        const int* ei = (const int*)ei_raw;
        s = ei[e];
        d = ei[(size_t)E + e];
    }
    if (s < 0) s = 0; if (s >= n) s = n - 1;
    if (d < 0) d = 0; if (d >= n) d = n - 1;
    g_edge[e] = make_int2(s, d);
    atomicAdd(&g_deg[d], 1);
}

// ---------------- fused GEMM -------------------------------------------------
// g[r][c] = dis[r] * sum_k pre(X[r][k]) * W[k][c],  dis[r] = rsqrt(deg[r])
// pre(x)  = PRE ? relu(dis[r]*x + preb[k]) : x
// dual store: g -> gout, and same value -> acc (self-loop init, replaces memset)
// inner loop: k chunked by 4, X read via LDS.128 (4x fewer shared-mem ops)
template <bool PRE>
__global__ void __launch_bounds__(256) gemm_kernel(
    const float* __restrict__ X, const float* __restrict__ W,
    const float* __restrict__ preb, float* __restrict__ gout,
    float* __restrict__ acc, int n)
{
    __shared__ float Xs[64 * DD];

    const int tid  = threadIdx.x;
    const int row0 = blockIdx.x * 64;

    const float4* X4  = (const float4*)X;
    float4*       Xs4 = (float4*)Xs;
    #pragma unroll
    for (int i = tid; i < 64 * 32; i += 256) {
        int r  = i >> 5;
        int c4 = i & 31;
        int gr = row0 + r;
        float4 v = make_float4(0.f, 0.f, 0.f, 0.f);
        if (gr < n) {
            v = X4[(size_t)gr * 32 + c4];
            if (PRE) {
                float dr = rsqrtf((float)__ldg(&g_deg[gr]));
                float4 bb = ((const float4*)preb)[c4];
                v.x = fmaxf(fmaf(dr, v.x, bb.x), 0.f);
                v.y = fmaxf(fmaf(dr, v.y, bb.y), 0.f);
                v.z = fmaxf(fmaf(dr, v.z, bb.z), 0.f);
                v.w = fmaxf(fmaf(dr, v.w, bb.w), 0.f);
            }
        }
        Xs4[i] = v;
    }
    __syncthreads();

    const int tx = tid & 31;   // output col group: cols 4*tx..4*tx+3
    const int ty = tid >> 5;   // row group: rows ty*8..ty*8+7

    unsigned long long accr[8][2];
    #pragma unroll
    for (int r = 0; r < 8; r++) { accr[r][0] = 0ull; accr[r][1] = 0ull; }

    const float4* W4   = (const float4*)W;
    const float4* Xs4r = (const float4*)Xs;

    #pragma unroll 2
    for (int kc = 0; kc < 32; kc++) {           // 4 k-values per chunk
        float4 w0 = __ldg(&W4[(kc * 4 + 0) * 32 + tx]);
        float4 w1 = __ldg(&W4[(kc * 4 + 1) * 32 + tx]);
        float4 w2 = __ldg(&W4[(kc * 4 + 2) * 32 + tx]);
        float4 w3 = __ldg(&W4[(kc * 4 + 3) * 32 + tx]);
        unsigned long long wp[4][2];
        wp[0][0] = pack2(w0.x, w0.y); wp[0][1] = pack2(w0.z, w0.w);
        wp[1][0] = pack2(w1.x, w1.y); wp[1][1] = pack2(w1.z, w1.w);
        wp[2][0] = pack2(w2.x, w2.y); wp[2][1] = pack2(w2.z, w2.w);
        wp[3][0] = pack2(w3.x, w3.y); wp[3][1] = pack2(w3.z, w3.w);

        #pragma unroll
        for (int r = 0; r < 8; r++) {
            float4 xv = Xs4r[(ty * 8 + r) * 32 + kc];   // LDS.128: k..k+3
            unsigned long long xp;
            xp = pack2(xv.x, xv.x);
            fma2(accr[r][0], xp, wp[0][0]); fma2(accr[r][1], xp, wp[0][1]);
            xp = pack2(xv.y, xv.y);
            fma2(accr[r][0], xp, wp[1][0]); fma2(accr[r][1], xp, wp[1][1]);
            xp = pack2(xv.z, xv.z);
            fma2(accr[r][0], xp, wp[2][0]); fma2(accr[r][1], xp, wp[2][1]);
            xp = pack2(xv.w, xv.w);
            fma2(accr[r][0], xp, wp[3][0]); fma2(accr[r][1], xp, wp[3][1]);
        }
    }

    #pragma unroll
    for (int r = 0; r < 8; r++) {
        int gr = row0 + ty * 8 + r;
        if (gr < n) {
            float ds = rsqrtf((float)__ldg(&g_deg[gr]));
            float a0, a1, a2, a3;
            unpack2(accr[r][0], a0, a1);
            unpack2(accr[r][1], a2, a3);
            float4 o = make_float4(a0 * ds, a1 * ds, a2 * ds, a3 * ds);
            ((float4*)gout)[(size_t)gr * 32 + tx] = o;
            ((float4*)acc )[(size_t)gr * 32 + tx] = o;   // self-loop init
        }
    }
}

// ---------------- scatter: acc[dst] += g[src], warp per edge -----------------
__global__ void __launch_bounds__(256) scatter_kernel(
    const float* __restrict__ g, float* __restrict__ acc, int E)
{
    int warp = (blockIdx.x * blockDim.x + threadIdx.x) >> 5;
    int lane = threadIdx.x & 31;
    if (warp >= E) return;
    int2 e = g_edge[warp];

    float4 v = ((const float4*)(g + (size_t)e.x * DD))[lane];
    float* p = acc + (size_t)e.y * DD + lane * 4;
    asm volatile("red.global.add.v4.f32 [%0], {%1, %2, %3, %4};"
                 :: "l"(p), "f"(v.x), "f"(v.y), "f"(v.z), "f"(v.w)
                 : "memory");
}

// ---------------- finalize: out = relu(rsqrt(deg[r])*out + b2[c]) ------------
__global__ void finalize_kernel(float* __restrict__ out,
                                const float* __restrict__ b, int n)
{
    int i = blockIdx.x * blockDim.x + threadIdx.x;
    int total = n * DD;
    if (i >= total) return;
    int r = i >> 7;
    int c = i & 127;
    float ds = rsqrtf((float)g_deg[r]);
    out[i] = fmaxf(fmaf(ds, out[i], b[c]), 0.f);
}

// ---------------- launch -----------------------------------------------------
extern "C" void kernel_launch(void* const* d_in, const int* in_sizes, int n_in,
                              void* d_out, int out_size)
{
    const float* x   = (const float*)d_in[0];
    const void*  ei  = d_in[1];
    const float* W1  = (const float*)d_in[2];
    const float* b1  = (const float*)d_in[3];
    const float* W2  = (const float*)d_in[4];
    const float* b2  = (const float*)d_in[5];
    float*       out = (float*)d_out;

    const int n = in_sizes[0] / DD;   // 50000
    const int E = in_sizes[1] / 2;    // 800000

    void *pA = nullptr, *pB = nullptr;
    cudaGetSymbolAddress(&pA, g_bufA);
    cudaGetSymbolAddress(&pB, g_bufB);
    float* bufA = (float*)pA;
    float* bufB = (float*)pB;

    const int T = 256;
    const int gemm_grid = (n + 63) / 64;
    const int scat_grid = (E * 32 + T - 1) / T;   // warp per edge

    // (1) detect dtype + deg init   (2) decode edges + degree
    detect_init_kernel<<<(n + T - 1) / T, T>>>((const int*)ei, n);
    prep_edges_kernel<<<(E + T - 1) / T, T>>>(ei, E, n);

    // (3) layer-1 GEMM: g1 = (x@W1)*dis, acc1 initialized with self-loop
    gemm_kernel<false><<<gemm_grid, T>>>(x, W1, nullptr, bufA, bufB, n);
    // (4) layer-1 scatter  <-- profiled slot
    scatter_kernel<<<scat_grid, T>>>(bufA, bufB, E);

    // (5) layer-2 GEMM (relu(dis*acc1+b1) fused into tile load), acc2=out
    gemm_kernel<true><<<gemm_grid, T>>>(bufB, W2, b1, bufA, out, n);
    // (6) layer-2 scatter
    scatter_kernel<<<scat_grid, T>>>(bufA, out, E);

    // (7) out = relu(dis*acc2 + b2)
    finalize_kernel<<<((n * DD) + T - 1) / T, T>>>(out, b2, n);
}

// round 8
// speedup vs baseline: 1.3078x; 1.0051x over previous
#include <cuda_runtime.h>
#include <cuda_bf16.h>

#define NN 50000
#define EE 800000
#define DD 128

// ---------------- scratch (device globals: no allocation allowed) ----------
__device__ float g_bufA[(size_t)NN * DD];   // GEMM output g (per layer)
__device__ float g_bufB[(size_t)NN * DD];   // layer-1 accumulator
__device__ float g_dis[NN];
__device__ int   g_deg[NN];
__device__ int2  g_edge[EE];                // (src, dst)
__device__ int   g_is64;

// ---------------- f32x2 helpers (sm_103a packed fp32) ----------------------
__device__ __forceinline__ unsigned long long pack2(float lo, float hi) {
    unsigned long long r;
    asm("mov.b64 %0, {%1, %2};" : "=l"(r) : "f"(lo), "f"(hi));
    return r;
}
__device__ __forceinline__ void unpack2(unsigned long long v, float& lo, float& hi) {
    asm("mov.b64 {%0, %1}, %2;" : "=f"(lo), "=f"(hi) : "l"(v));
}
__device__ __forceinline__ void fma2(unsigned long long& acc,
                                     unsigned long long a, unsigned long long b) {
    asm("fma.rn.f32x2 %0, %1, %2, %3;" : "=l"(acc) : "l"(a), "l"(b), "l"(acc));
}

// ---------------- (1) dtype detect + deg init -------------------------------
// edge_index declared int64, but JAX w/o x64 silently emits int32. For int64
// LE values < 50000, every odd 32-bit word is 0.
__global__ void detect_init_kernel(const int* __restrict__ ei32, int n) {
    int i = blockIdx.x * blockDim.x + threadIdx.x;
    if (i < n) g_deg[i] = 1;  // self-loop
    if (i == 0) {
        int is64 = 1;
        for (int k = 0; k < 64; k++)
            if (ei32[2 * k + 1] != 0) { is64 = 0; break; }
        g_is64 = is64;
    }
}

// ---------------- (2) decode edges + dst degree ------------------------------
__global__ void prep_edges_kernel(const void* __restrict__ ei_raw, int E, int n) {
    int e = blockIdx.x * blockDim.x + threadIdx.x;
    if (e >= E) return;
    int s, d;
    if (g_is64) {
        const long long* ei = (const long long*)ei_raw;
        s = (int)ei[e];
        d = (int)ei[(size_t)E + e];
    } else {
        const int* ei = (const int*)ei_raw;
        s = ei[e];
        d = ei[(size_t)E + e];
    }
    if (s < 0) s = 0; if (s >= n) s = n - 1;
    if (d < 0) d = 0; if (d >= n) d = n - 1;
    g_edge[e] = make_int2(s, d);
    atomicAdd(&g_deg[d], 1);
}

// ---------------- (3) dis = rsqrt(deg) ---------------------------------------
__global__ void calc_dis_kernel(int n) {
    int i = blockIdx.x * blockDim.x + threadIdx.x;
    if (i < n) g_dis[i] = rsqrtf((float)g_deg[i]);
}

// ---------------- (4) fused GEMM ---------------------------------------------
// g[r][c] = dis[r] * sum_k pre(X[r][k]) * W[k][c]
// pre(x)  = PRE ? relu(dis[r]*x + preb[k]) : x
// dual store: g -> gout, and same value -> acc (self-loop init, replaces memset)
// inner loop: k chunked by 4; X via LDS.128 broadcast; W as raw ulonglong2
// (consecutive col pairs reinterpretated -- zero pack instructions for W)
template <bool PRE>
__global__ void __launch_bounds__(256) gemm_kernel(
    const float* __restrict__ X, const float* __restrict__ W,
    const float* __restrict__ preb, float* __restrict__ gout,
    float* __restrict__ acc, int n)
{
    __shared__ float Xs[64 * DD];

    const int tid  = threadIdx.x;
    const int row0 = blockIdx.x * 64;

    const float4* X4  = (const float4*)X;
    float4*       Xs4 = (float4*)Xs;
    #pragma unroll
    for (int i = tid; i < 64 * 32; i += 256) {
        int r  = i >> 5;
        int c4 = i & 31;
        int gr = row0 + r;
        float4 v = make_float4(0.f, 0.f, 0.f, 0.f);
        if (gr < n) {
            v = X4[(size_t)gr * 32 + c4];
            if (PRE) {
                float dr = g_dis[gr];
                float4 bb = ((const float4*)preb)[c4];
                v.x = fmaxf(fmaf(dr, v.x, bb.x), 0.f);
                v.y = fmaxf(fmaf(dr, v.y, bb.y), 0.f);
                v.z = fmaxf(fmaf(dr, v.z, bb.z), 0.f);
                v.w = fmaxf(fmaf(dr, v.w, bb.w), 0.f);
            }
        }
        Xs4[i] = v;
    }
    __syncthreads();

    const int tx = tid & 31;   // output col group: cols 4*tx..4*tx+3
    const int ty = tid >> 5;   // row group: rows ty*8..ty*8+7

    unsigned long long accr[8][2];
    #pragma unroll
    for (int r = 0; r < 8; r++) { accr[r][0] = 0ull; accr[r][1] = 0ull; }

    // W rows reinterpreted as pairs: W16[k*32 + tx] = {(w[4tx],w[4tx+1]), (w[4tx+2],w[4tx+3])}
    const ulonglong2* __restrict__ W16 = (const ulonglong2*)W;
    const float4*     __restrict__ Xs4r = (const float4*)Xs;

    #pragma unroll 2
    for (int kc = 0; kc < 32; kc++) {           // 4 k-values per chunk
        ulonglong2 w0 = __ldg(&W16[(kc * 4 + 0) * 32 + tx]);
        ulonglong2 w1 = __ldg(&W16[(kc * 4 + 1) * 32 + tx]);
        ulonglong2 w2 = __ldg(&W16[(kc * 4 + 2) * 32 + tx]);
        ulonglong2 w3 = __ldg(&W16[(kc * 4 + 3) * 32 + tx]);

        #pragma unroll
        for (int r = 0; r < 8; r++) {
            float4 xv = Xs4r[(ty * 8 + r) * 32 + kc];   // LDS.128 broadcast: k..k+3
            unsigned long long xp;
            xp = pack2(xv.x, xv.x);
            fma2(accr[r][0], xp, w0.x); fma2(accr[r][1], xp, w0.y);
            xp = pack2(xv.y, xv.y);
            fma2(accr[r][0], xp, w1.x); fma2(accr[r][1], xp, w1.y);
            xp = pack2(xv.z, xv.z);
            fma2(accr[r][0], xp, w2.x); fma2(accr[r][1], xp, w2.y);
            xp = pack2(xv.w, xv.w);
            fma2(accr[r][0], xp, w3.x); fma2(accr[r][1], xp, w3.y);
        }
    }

    #pragma unroll
    for (int r = 0; r < 8; r++) {
        int gr = row0 + ty * 8 + r;
        if (gr < n) {
            float ds = g_dis[gr];
            float a0, a1, a2, a3;
            unpack2(accr[r][0], a0, a1);
            unpack2(accr[r][1], a2, a3);
            float4 o = make_float4(a0 * ds, a1 * ds, a2 * ds, a3 * ds);
            ((float4*)gout)[(size_t)gr * 32 + tx] = o;
            ((float4*)acc )[(size_t)gr * 32 + tx] = o;   // self-loop init
        }
    }
}

// ---------------- scatter: acc[dst] += g[src], warp per edge -----------------
__global__ void __launch_bounds__(256) scatter_kernel(
    const float* __restrict__ g, float* __restrict__ acc, int E)
{
    int warp = (blockIdx.x * blockDim.x + threadIdx.x) >> 5;
    int lane = threadIdx.x & 31;
    if (warp >= E) return;
    int2 e = g_edge[warp];

    float4 v = ((const float4*)(g + (size_t)e.x * DD))[lane];
    float* p = acc + (size_t)e.y * DD + lane * 4;
    asm volatile("red.global.add.v4.f32 [%0], {%1, %2, %3, %4};"
                 :: "l"(p), "f"(v.x), "f"(v.y), "f"(v.z), "f"(v.w)
                 : "memory");
}

// ---------------- finalize: out = relu(dis[r]*out + b2[c]) -------------------
__global__ void finalize_kernel(float* __restrict__ out,
                                const float* __restrict__ b, int n)
{
    int i = blockIdx.x * blockDim.x + threadIdx.x;
    int total = n * DD;
    if (i >= total) return;
    int r = i >> 7;
    int c = i & 127;
    out[i] = fmaxf(fmaf(g_dis[r], out[i], b[c]), 0.f);
}

// ---------------- launch -----------------------------------------------------
extern "C" void kernel_launch(void* const* d_in, const int* in_sizes, int n_in,
                              void* d_out, int out_size)
{
    const float* x   = (const float*)d_in[0];
    const void*  ei  = d_in[1];
    const float* W1  = (const float*)d_in[2];
    const float* b1  = (const float*)d_in[3];
    const float* W2  = (const float*)d_in[4];
    const float* b2  = (const float*)d_in[5];
    float*       out = (float*)d_out;

    const int n = in_sizes[0] / DD;   // 50000
    const int E = in_sizes[1] / 2;    // 800000

    void *pA = nullptr, *pB = nullptr;
    cudaGetSymbolAddress(&pA, g_bufA);
    cudaGetSymbolAddress(&pB, g_bufB);
    float* bufA = (float*)pA;
    float* bufB = (float*)pB;

    const int T = 256;
    const int gemm_grid = (n + 63) / 64;
    const int scat_grid = (E * 32 + T - 1) / T;   // warp per edge

    // (1) detect + deg init    (2) decode + degree     (3) dis
    detect_init_kernel<<<(n + T - 1) / T, T>>>((const int*)ei, n);
    prep_edges_kernel<<<(E + T - 1) / T, T>>>(ei, E, n);
    calc_dis_kernel<<<(n + T - 1) / T, T>>>(n);

    // (4) layer-1 GEMM  <-- profiled slot (launch #4)
    gemm_kernel<false><<<gemm_grid, T>>>(x, W1, nullptr, bufA, bufB, n);
    // (5) layer-1 scatter
    scatter_kernel<<<scat_grid, T>>>(bufA, bufB, E);

    // (6) layer-2 GEMM (relu(dis*acc1+b1) fused into tile load), acc2=out
    gemm_kernel<true><<<gemm_grid, T>>>(bufB, W2, b1, bufA, out, n);
    // (7) layer-2 scatter
    scatter_kernel<<<scat_grid, T>>>(bufA, out, E);

    // (8) out = relu(dis*acc2 + b2)
    finalize_kernel<<<((n * DD) + T - 1) / T, T>>>(out, b2, n);
}